// round 12
// baseline (speedup 1.0000x reference)
#include <cuda_runtime.h>

// y[t, f] = x[t, f] * w[f] + b[f]
// x: [8192, 4096] f32 (134 MB), w/b: [4096] f32, out: f32 (134 MB).
//
// FINAL (R1 shape, best + most repeatable across 10 rounds).
// Evidence: compulsory 268.4 MB HBM traffic; every well-occupied 256-thread
// stream shape lands at 43.5-45 us (bench noise +/-1.5 us) = ~6.17 TB/s
// sustained mixed read/write — the HBM controller wall. L2 residency tricks
// regress (no persisting carveout available); 512-thread blocks regress
// (occupancy quantization). Simplest wall-rate kernel:
//   - one LDG.128 + one STG.128 per thread, perfectly coalesced
//   - w/b (16 KB each) L1-resident via __ldg, column = i & 1023
//   - 256-thread blocks, exact-cover grid (32768 blocks), 26 regs

static constexpr int TOKENS = 8192;
static constexpr int FEATURES = 4096;
static constexpr int F4_PER_ROW = FEATURES / 4;          // 1024
static constexpr int TOTAL_F4 = TOKENS * F4_PER_ROW;     // 8,388,608

__global__ void __launch_bounds__(256) one_to_one_kernel(
    const float4* __restrict__ x,
    const float4* __restrict__ w,
    const float4* __restrict__ b,
    float4* __restrict__ out)
{
    int i = blockIdx.x * blockDim.x + threadIdx.x;
    if (i >= TOTAL_F4) return;

    int c = i & (F4_PER_ROW - 1);   // column in float4 units

    float4 xv = x[i];
    float4 wv = __ldg(&w[c]);
    float4 bv = __ldg(&b[c]);

    float4 r;
    r.x = fmaf(xv.x, wv.x, bv.x);
    r.y = fmaf(xv.y, wv.y, bv.y);
    r.z = fmaf(xv.z, wv.z, bv.z);
    r.w = fmaf(xv.w, wv.w, bv.w);

    out[i] = r;
}

extern "C" void kernel_launch(void* const* d_in, const int* in_sizes, int n_in,
                              void* d_out, int out_size)
{
    const float4* x = (const float4*)d_in[0];
    const float4* w = (const float4*)d_in[1];
    const float4* b = (const float4*)d_in[2];
    float4* out = (float4*)d_out;

    const int threads = 256;
    const int blocks = (TOTAL_F4 + threads - 1) / threads;  // 32768
    one_to_one_kernel<<<blocks, threads>>>(x, w, b, out);
}

// round 13
// speedup vs baseline: 1.0471x; 1.0471x over previous
#include <cuda_runtime.h>
#include <cstdint>

// y[t, f] = x[t, f] * w[f] + b[f]
// x: [8192, 4096] f32 (134 MB), w/b: [4096] f32, out: f32 (134 MB).
//
// Fully 256-bit stream: one ld.global.nc.v8.b32 + one st.global.v8.b32 per
// thread (8 contiguous floats). Minimal SM-side cost at the HBM controller
// wall (~6.17 TB/s sustained mixed r/w; 268.4 MB compulsory traffic).
// w/b (16 KB each) L1-resident via __ldg. 256-thread blocks, 16384 blocks.

static constexpr int TOKENS = 8192;
static constexpr int FEATURES = 4096;
static constexpr int F8_PER_ROW = FEATURES / 8;                // 512
static constexpr int TOTAL_G8 = TOKENS * F8_PER_ROW;           // 4,194,304

__device__ __forceinline__ void ldg256(const float* p, float4& lo, float4& hi) {
    uint32_t u0,u1,u2,u3,u4,u5,u6,u7;
    asm volatile("ld.global.nc.v8.b32 {%0,%1,%2,%3,%4,%5,%6,%7}, [%8];"
                 : "=r"(u0),"=r"(u1),"=r"(u2),"=r"(u3),
                   "=r"(u4),"=r"(u5),"=r"(u6),"=r"(u7)
                 : "l"(p));
    lo.x=__uint_as_float(u0); lo.y=__uint_as_float(u1);
    lo.z=__uint_as_float(u2); lo.w=__uint_as_float(u3);
    hi.x=__uint_as_float(u4); hi.y=__uint_as_float(u5);
    hi.z=__uint_as_float(u6); hi.w=__uint_as_float(u7);
}

__device__ __forceinline__ void stg256(float* p, const float4& lo, const float4& hi) {
    asm volatile("st.global.v8.b32 [%0], {%1,%2,%3,%4,%5,%6,%7,%8};"
                 :: "l"(p),
                    "r"(__float_as_uint(lo.x)), "r"(__float_as_uint(lo.y)),
                    "r"(__float_as_uint(lo.z)), "r"(__float_as_uint(lo.w)),
                    "r"(__float_as_uint(hi.x)), "r"(__float_as_uint(hi.y)),
                    "r"(__float_as_uint(hi.z)), "r"(__float_as_uint(hi.w))
                 : "memory");
}

__global__ void __launch_bounds__(256) one_to_one_kernel(
    const float* __restrict__ x,
    const float* __restrict__ w,
    const float* __restrict__ b,
    float* __restrict__ out)
{
    int i = blockIdx.x * blockDim.x + threadIdx.x;
    if (i >= TOTAL_G8) return;

    int c8 = i & (F8_PER_ROW - 1);       // column in 8-float units
    long base = (long)i * 8;             // contiguous across rows

    float4 xlo, xhi;
    ldg256(x + base, xlo, xhi);

    const float4* w4 = (const float4*)(w + c8 * 8);
    const float4* b4 = (const float4*)(b + c8 * 8);
    float4 wlo = __ldg(w4), whi = __ldg(w4 + 1);
    float4 blo = __ldg(b4), bhi = __ldg(b4 + 1);

    float4 rlo, rhi;
    rlo.x = fmaf(xlo.x, wlo.x, blo.x);
    rlo.y = fmaf(xlo.y, wlo.y, blo.y);
    rlo.z = fmaf(xlo.z, wlo.z, blo.z);
    rlo.w = fmaf(xlo.w, wlo.w, blo.w);
    rhi.x = fmaf(xhi.x, whi.x, bhi.x);
    rhi.y = fmaf(xhi.y, whi.y, bhi.y);
    rhi.z = fmaf(xhi.z, whi.z, bhi.z);
    rhi.w = fmaf(xhi.w, whi.w, bhi.w);

    stg256(out + base, rlo, rhi);
}

extern "C" void kernel_launch(void* const* d_in, const int* in_sizes, int n_in,
                              void* d_out, int out_size)
{
    const float* x = (const float*)d_in[0];
    const float* w = (const float*)d_in[1];
    const float* b = (const float*)d_in[2];
    float* out = (float*)d_out;

    const int threads = 256;
    const int blocks = (TOTAL_G8 + threads - 1) / threads;     // 16384
    one_to_one_kernel<<<blocks, threads>>>(x, w, b, out);
}